// round 7
// baseline (speedup 1.0000x reference)
#include <cuda_runtime.h>
#include <cuda_bf16.h>

#define NMAX 100000
#define EMAX 1250000
#define DD 64

// ---------------- scratch ----------------
__device__ int   g_degi[NMAX];
__device__ float g_dis[NMAX];
__device__ int   g_rowptr[NMAX + 1];
__device__ int   g_cursor[NMAX];
__device__ int   g_csr[EMAX];
__device__ int   g_blocksums[512];
__device__ float g_bufA[(size_t)NMAX * DD];
__device__ float g_bufB[(size_t)NMAX * DD];
__device__ float g_bufC[(size_t)NMAX * DD];

// ---------------- tf32 helpers ----------------
__device__ __forceinline__ unsigned f2tf(float f) {
    unsigned u;
    asm("cvt.rna.tf32.f32 %0, %1;" : "=r"(u) : "f"(f));
    return u;
}
__device__ __forceinline__ void mma8(float c[4], unsigned a0, unsigned a1, unsigned a2,
                                     unsigned a3, unsigned b0, unsigned b1) {
    asm("mma.sync.aligned.m16n8k8.row.col.f32.tf32.tf32.f32 "
        "{%0,%1,%2,%3},{%4,%5,%6,%7},{%8,%9},{%0,%1,%2,%3};"
        : "+f"(c[0]), "+f"(c[1]), "+f"(c[2]), "+f"(c[3])
        : "r"(a0), "r"(a1), "r"(a2), "r"(a3), "r"(b0), "r"(b1));
}

// ---------------- degree ----------------
__global__ void deg_count_kernel(const int* __restrict__ dst, int E, int* __restrict__ degi) {
    int i = blockIdx.x * blockDim.x + threadIdx.x;
    if (i < E) atomicAdd(&degi[dst[i]], 1);
}

// ---------------- exclusive scan (n <= 512*512), fused dis ----------------
__global__ void scan1_kernel(const int* __restrict__ cnt, int* __restrict__ out,
                             int* __restrict__ bsums, float* __restrict__ dis, int n) {
    __shared__ int s[512];
    int i = blockIdx.x * 512 + threadIdx.x;
    int v = (i < n) ? cnt[i] : 0;
    if (i < n) dis[i] = rsqrtf((float)v + 1.0f);
    s[threadIdx.x] = v;
    __syncthreads();
    for (int off = 1; off < 512; off <<= 1) {
        int t = (threadIdx.x >= off) ? s[threadIdx.x - off] : 0;
        __syncthreads();
        s[threadIdx.x] += t;
        __syncthreads();
    }
    if (i < n) out[i] = s[threadIdx.x] - v;
    if (threadIdx.x == 511) bsums[blockIdx.x] = s[511];
}
__global__ void scan2_kernel(int* __restrict__ bsums, int nb) {
    __shared__ int s[512];
    int v = (threadIdx.x < nb) ? bsums[threadIdx.x] : 0;
    s[threadIdx.x] = v;
    __syncthreads();
    for (int off = 1; off < 512; off <<= 1) {
        int t = (threadIdx.x >= off) ? s[threadIdx.x - off] : 0;
        __syncthreads();
        s[threadIdx.x] += t;
        __syncthreads();
    }
    if (threadIdx.x < nb) bsums[threadIdx.x] = s[threadIdx.x] - v;
}
__global__ void scan3_kernel(int* __restrict__ rowptr, const int* __restrict__ bsums,
                             int* __restrict__ cursor, int n, int E) {
    int i = blockIdx.x * 512 + threadIdx.x;
    if (i < n) {
        int v = rowptr[i] + bsums[blockIdx.x];
        rowptr[i] = v;
        cursor[i] = v;
    }
    if (i == n) rowptr[n] = E;
}
__global__ void fill_csr_kernel(const int* __restrict__ src, const int* __restrict__ dst,
                                int* __restrict__ cursor, int* __restrict__ csr, int E) {
    int i = blockIdx.x * blockDim.x + threadIdx.x;
    if (i < E) {
        int pos = atomicAdd(&cursor[dst[i]], 1);
        csr[pos] = src[i];
    }
}

// ---------------- dual-node gather (CSR), interleaved for MLP ----------------
// Block covers 32 nodes; 16-thread group g handles nodes base+g and base+16+g.
template <bool GCN, bool RELU>
__global__ void __launch_bounds__(256) gather_kernel(
    const int* __restrict__ rowptr, const int* __restrict__ csr,
    const float* __restrict__ xw, const float* __restrict__ dis,
    const float* __restrict__ bias, float* __restrict__ out, int n) {
    int g = threadIdx.x >> 4;          // 0..15
    int q = threadIdx.x & 15;
    int nodeA = blockIdx.x * 32 + g;
    int nodeB = nodeA + 16;
    const float4* __restrict__ xwv = (const float4*)xw;

    bool vA = nodeA < n, vB = nodeB < n;
    int begA = 0, endA = 0, begB = 0, endB = 0;
    if (vA) { begA = rowptr[nodeA]; endA = rowptr[nodeA + 1]; }
    if (vB) { begB = rowptr[nodeB]; endB = rowptr[nodeB + 1]; }

    float4 accA = make_float4(0.f, 0.f, 0.f, 0.f);
    float4 accB = make_float4(0.f, 0.f, 0.f, 0.f);

    int eA = begA, eB = begB;
    // interleaved main loop: up to 4+4 loads in flight
    while (eA + 3 < endA && eB + 3 < endB) {
        int a0 = csr[eA], a1 = csr[eA + 1], a2 = csr[eA + 2], a3 = csr[eA + 3];
        int b0 = csr[eB], b1 = csr[eB + 1], b2 = csr[eB + 2], b3 = csr[eB + 3];
        float4 va0 = xwv[a0 * 16 + q], va1 = xwv[a1 * 16 + q];
        float4 va2 = xwv[a2 * 16 + q], va3 = xwv[a3 * 16 + q];
        float4 vb0 = xwv[b0 * 16 + q], vb1 = xwv[b1 * 16 + q];
        float4 vb2 = xwv[b2 * 16 + q], vb3 = xwv[b3 * 16 + q];
        if (GCN) {
            float wa0 = dis[a0], wa1 = dis[a1], wa2 = dis[a2], wa3 = dis[a3];
            float wb0 = dis[b0], wb1 = dis[b1], wb2 = dis[b2], wb3 = dis[b3];
            accA.x += va0.x * wa0 + va1.x * wa1 + va2.x * wa2 + va3.x * wa3;
            accA.y += va0.y * wa0 + va1.y * wa1 + va2.y * wa2 + va3.y * wa3;
            accA.z += va0.z * wa0 + va1.z * wa1 + va2.z * wa2 + va3.z * wa3;
            accA.w += va0.w * wa0 + va1.w * wa1 + va2.w * wa2 + va3.w * wa3;
            accB.x += vb0.x * wb0 + vb1.x * wb1 + vb2.x * wb2 + vb3.x * wb3;
            accB.y += vb0.y * wb0 + vb1.y * wb1 + vb2.y * wb2 + vb3.y * wb3;
            accB.z += vb0.z * wb0 + vb1.z * wb1 + vb2.z * wb2 + vb3.z * wb3;
            accB.w += vb0.w * wb0 + vb1.w * wb1 + vb2.w * wb2 + vb3.w * wb3;
        } else {
            accA.x += (va0.x + va1.x) + (va2.x + va3.x);
            accA.y += (va0.y + va1.y) + (va2.y + va3.y);
            accA.z += (va0.z + va1.z) + (va2.z + va3.z);
            accA.w += (va0.w + va1.w) + (va2.w + va3.w);
            accB.x += (vb0.x + vb1.x) + (vb2.x + vb3.x);
            accB.y += (vb0.y + vb1.y) + (vb2.y + vb3.y);
            accB.z += (vb0.z + vb1.z) + (vb2.z + vb3.z);
            accB.w += (vb0.w + vb1.w) + (vb2.w + vb3.w);
        }
        eA += 4; eB += 4;
    }
    // drain A
    for (; eA + 3 < endA; eA += 4) {
        int a0 = csr[eA], a1 = csr[eA + 1], a2 = csr[eA + 2], a3 = csr[eA + 3];
        float4 va0 = xwv[a0 * 16 + q], va1 = xwv[a1 * 16 + q];
        float4 va2 = xwv[a2 * 16 + q], va3 = xwv[a3 * 16 + q];
        if (GCN) {
            float wa0 = dis[a0], wa1 = dis[a1], wa2 = dis[a2], wa3 = dis[a3];
            accA.x += va0.x * wa0 + va1.x * wa1 + va2.x * wa2 + va3.x * wa3;
            accA.y += va0.y * wa0 + va1.y * wa1 + va2.y * wa2 + va3.y * wa3;
            accA.z += va0.z * wa0 + va1.z * wa1 + va2.z * wa2 + va3.z * wa3;
            accA.w += va0.w * wa0 + va1.w * wa1 + va2.w * wa2 + va3.w * wa3;
        } else {
            accA.x += (va0.x + va1.x) + (va2.x + va3.x);
            accA.y += (va0.y + va1.y) + (va2.y + va3.y);
            accA.z += (va0.z + va1.z) + (va2.z + va3.z);
            accA.w += (va0.w + va1.w) + (va2.w + va3.w);
        }
    }
    // drain B
    for (; eB + 3 < endB; eB += 4) {
        int b0 = csr[eB], b1 = csr[eB + 1], b2 = csr[eB + 2], b3 = csr[eB + 3];
        float4 vb0 = xwv[b0 * 16 + q], vb1 = xwv[b1 * 16 + q];
        float4 vb2 = xwv[b2 * 16 + q], vb3 = xwv[b3 * 16 + q];
        if (GCN) {
            float wb0 = dis[b0], wb1 = dis[b1], wb2 = dis[b2], wb3 = dis[b3];
            accB.x += vb0.x * wb0 + vb1.x * wb1 + vb2.x * wb2 + vb3.x * wb3;
            accB.y += vb0.y * wb0 + vb1.y * wb1 + vb2.y * wb2 + vb3.y * wb3;
            accB.z += vb0.z * wb0 + vb1.z * wb1 + vb2.z * wb2 + vb3.z * wb3;
            accB.w += vb0.w * wb0 + vb1.w * wb1 + vb2.w * wb2 + vb3.w * wb3;
        } else {
            accB.x += (vb0.x + vb1.x) + (vb2.x + vb3.x);
            accB.y += (vb0.y + vb1.y) + (vb2.y + vb3.y);
            accB.z += (vb0.z + vb1.z) + (vb2.z + vb3.z);
            accB.w += (vb0.w + vb1.w) + (vb2.w + vb3.w);
        }
    }
    // scalar remainders (interleave the two to keep 2 loads in flight)
    while (eA < endA || eB < endB) {
        if (eA < endA) {
            int s = csr[eA++];
            float4 v = xwv[s * 16 + q];
            float w = GCN ? dis[s] : 1.0f;
            accA.x += v.x * w; accA.y += v.y * w; accA.z += v.z * w; accA.w += v.w * w;
        }
        if (eB < endB) {
            int s = csr[eB++];
            float4 v = xwv[s * 16 + q];
            float w = GCN ? dis[s] : 1.0f;
            accB.x += v.x * w; accB.y += v.y * w; accB.z += v.z * w; accB.w += v.w * w;
        }
    }

    // epilogues
    if (vA) {
        float4 acc = accA;
        if (GCN) {
            float dd = dis[nodeA];
            float d2 = dd * dd;
            float4 xv = xwv[nodeA * 16 + q];
            float4 bb = ((const float4*)bias)[q];
            acc.x = fmaf(acc.x, dd, fmaf(xv.x, d2, bb.x));
            acc.y = fmaf(acc.y, dd, fmaf(xv.y, d2, bb.y));
            acc.z = fmaf(acc.z, dd, fmaf(xv.z, d2, bb.z));
            acc.w = fmaf(acc.w, dd, fmaf(xv.w, d2, bb.w));
            if (RELU) {
                acc.x = fmaxf(acc.x, 0.f); acc.y = fmaxf(acc.y, 0.f);
                acc.z = fmaxf(acc.z, 0.f); acc.w = fmaxf(acc.w, 0.f);
            }
        } else {
            float dinv = 1.0f / fmaxf((float)(endA - begA), 1.0f);
            acc.x *= dinv; acc.y *= dinv; acc.z *= dinv; acc.w *= dinv;
        }
        ((float4*)out)[nodeA * 16 + q] = acc;
    }
    if (vB) {
        float4 acc = accB;
        if (GCN) {
            float dd = dis[nodeB];
            float d2 = dd * dd;
            float4 xv = xwv[nodeB * 16 + q];
            float4 bb = ((const float4*)bias)[q];
            acc.x = fmaf(acc.x, dd, fmaf(xv.x, d2, bb.x));
            acc.y = fmaf(acc.y, dd, fmaf(xv.y, d2, bb.y));
            acc.z = fmaf(acc.z, dd, fmaf(xv.z, d2, bb.z));
            acc.w = fmaf(acc.w, dd, fmaf(xv.w, d2, bb.w));
            if (RELU) {
                acc.x = fmaxf(acc.x, 0.f); acc.y = fmaxf(acc.y, 0.f);
                acc.z = fmaxf(acc.z, 0.f); acc.w = fmaxf(acc.w, 0.f);
            }
        } else {
            float dinv = 1.0f / fmaxf((float)(endB - begB), 1.0f);
            acc.x *= dinv; acc.y *= dinv; acc.z *= dinv; acc.w *= dinv;
        }
        ((float4*)out)[nodeB * 16 + q] = acc;
    }
}

// ---------------- tensor-core GEMM: out = act(X @ W [+ b]) ----------------
#define XS_STRIDE 68
#define WS_STRIDE 72
template <bool RELU, bool BIAS>
__global__ void __launch_bounds__(256) gemm_tc_kernel(
    const float* __restrict__ X, const float* __restrict__ W,
    const float* __restrict__ bias, float* __restrict__ out, int n) {
    extern __shared__ char smraw[];
    float* Ws = (float*)smraw;
    float* Xs = (float*)(smraw + 64 * WS_STRIDE * 4);
    int tid = threadIdx.x;
    int row0 = blockIdx.x * 128;

    for (int i = tid; i < 4096; i += 256) {
        int k = i >> 6, c = i & 63;
        Ws[k * WS_STRIDE + c] = __uint_as_float(f2tf(W[i]));
    }
    for (int j = tid; j < 2048; j += 256) {
        int r = j >> 4, cg = j & 15;
        float4 v = (row0 + r < n) ? ((const float4*)X)[(size_t)(row0 + r) * 16 + cg]
                                  : make_float4(0.f, 0.f, 0.f, 0.f);
        float* p = &Xs[r * XS_STRIDE + cg * 4];
        p[0] = v.x; p[1] = v.y; p[2] = v.z; p[3] = v.w;
    }
    __syncthreads();

    int warp = tid >> 5;
    int lane = tid & 31;
    int gid = lane >> 2;
    int tig = lane & 3;
    int rlo = warp * 16 + gid;

    float c[8][4];
#pragma unroll
    for (int t = 0; t < 8; t++)
#pragma unroll
        for (int j = 0; j < 4; j++) c[t][j] = 0.f;

#pragma unroll
    for (int ks = 0; ks < 8; ks++) {
        int k0 = ks * 8;
        unsigned a0 = f2tf(Xs[rlo * XS_STRIDE + k0 + tig]);
        unsigned a1 = f2tf(Xs[(rlo + 8) * XS_STRIDE + k0 + tig]);
        unsigned a2 = f2tf(Xs[rlo * XS_STRIDE + k0 + tig + 4]);
        unsigned a3 = f2tf(Xs[(rlo + 8) * XS_STRIDE + k0 + tig + 4]);
#pragma unroll
        for (int t = 0; t < 8; t++) {
            int col = t * 8 + gid;
            unsigned b0 = __float_as_uint(Ws[(k0 + tig) * WS_STRIDE + col]);
            unsigned b1 = __float_as_uint(Ws[(k0 + tig + 4) * WS_STRIDE + col]);
            mma8(c[t], a0, a1, a2, a3, b0, b1);
        }
    }

#pragma unroll
    for (int t = 0; t < 8; t++) {
        int colp = t * 4 + tig;
        float2 bb = BIAS ? ((const float2*)bias)[colp] : make_float2(0.f, 0.f);
        int row_lo = row0 + warp * 16 + gid;
        int row_hi = row_lo + 8;
        if (row_lo < n) {
            float2 o = make_float2(c[t][0] + bb.x, c[t][1] + bb.y);
            if (RELU) { o.x = fmaxf(o.x, 0.f); o.y = fmaxf(o.y, 0.f); }
            ((float2*)out)[(size_t)row_lo * 32 + colp] = o;
        }
        if (row_hi < n) {
            float2 o = make_float2(c[t][2] + bb.x, c[t][3] + bb.y);
            if (RELU) { o.x = fmaxf(o.x, 0.f); o.y = fmaxf(o.y, 0.f); }
            ((float2*)out)[(size_t)row_hi * 32 + colp] = o;
        }
    }
}

// ---------------- tensor-core SAGE: out = act(M @ Wl + bl + H @ Wr + H) ----------------
template <bool RELU>
__global__ void __launch_bounds__(256) sage_tc_kernel(
    const float* __restrict__ M, const float* __restrict__ H,
    const float* __restrict__ Wl, const float* __restrict__ bl,
    const float* __restrict__ Wr, float* __restrict__ out, int n) {
    extern __shared__ char smraw[];
    float* Wc = (float*)smraw;
    float* Ms = (float*)(smraw + 128 * WS_STRIDE * 4);
    float* Hs = (float*)(smraw + 128 * WS_STRIDE * 4 + 128 * XS_STRIDE * 4);
    int tid = threadIdx.x;
    int row0 = blockIdx.x * 128;

    for (int i = tid; i < 4096; i += 256) {
        int k = i >> 6, cc = i & 63;
        Wc[k * WS_STRIDE + cc]        = __uint_as_float(f2tf(Wl[i]));
        Wc[(k + 64) * WS_STRIDE + cc] = __uint_as_float(f2tf(Wr[i]));
    }
    for (int j = tid; j < 2048; j += 256) {
        int r = j >> 4, cg = j & 15;
        float4 m = make_float4(0.f, 0.f, 0.f, 0.f), h = m;
        if (row0 + r < n) {
            m = ((const float4*)M)[(size_t)(row0 + r) * 16 + cg];
            h = ((const float4*)H)[(size_t)(row0 + r) * 16 + cg];
        }
        float* pm = &Ms[r * XS_STRIDE + cg * 4];
        float* ph = &Hs[r * XS_STRIDE + cg * 4];
        pm[0] = m.x; pm[1] = m.y; pm[2] = m.z; pm[3] = m.w;
        ph[0] = h.x; ph[1] = h.y; ph[2] = h.z; ph[3] = h.w;
    }
    __syncthreads();

    int warp = tid >> 5;
    int lane = tid & 31;
    int gid = lane >> 2;
    int tig = lane & 3;
    int rlo = warp * 16 + gid;

    float c[8][4];
#pragma unroll
    for (int t = 0; t < 8; t++)
#pragma unroll
        for (int j = 0; j < 4; j++) c[t][j] = 0.f;

#pragma unroll
    for (int ks = 0; ks < 16; ks++) {
        const float* A = (ks < 8) ? Ms : Hs;
        int k0 = (ks & 7) * 8;
        int kw = ks * 8;
        unsigned a0 = f2tf(A[rlo * XS_STRIDE + k0 + tig]);
        unsigned a1 = f2tf(A[(rlo + 8) * XS_STRIDE + k0 + tig]);
        unsigned a2 = f2tf(A[rlo * XS_STRIDE + k0 + tig + 4]);
        unsigned a3 = f2tf(A[(rlo + 8) * XS_STRIDE + k0 + tig + 4]);
#pragma unroll
        for (int t = 0; t < 8; t++) {
            int col = t * 8 + gid;
            unsigned b0 = __float_as_uint(Wc[(kw + tig) * WS_STRIDE + col]);
            unsigned b1 = __float_as_uint(Wc[(kw + tig + 4) * WS_STRIDE + col]);
            mma8(c[t], a0, a1, a2, a3, b0, b1);
        }
    }

#pragma unroll
    for (int t = 0; t < 8; t++) {
        int colp = t * 4 + tig;
        int col = colp * 2;
        float2 bb = ((const float2*)bl)[colp];
        int rl = warp * 16 + gid;
        int row_lo = row0 + rl;
        int row_hi = row_lo + 8;
        if (row_lo < n) {
            float2 o = make_float2(c[t][0] + bb.x + Hs[rl * XS_STRIDE + col],
                                   c[t][1] + bb.y + Hs[rl * XS_STRIDE + col + 1]);
            if (RELU) { o.x = fmaxf(o.x, 0.f); o.y = fmaxf(o.y, 0.f); }
            ((float2*)out)[(size_t)row_lo * 32 + colp] = o;
        }
        if (row_hi < n) {
            float2 o = make_float2(c[t][2] + bb.x + Hs[(rl + 8) * XS_STRIDE + col],
                                   c[t][3] + bb.y + Hs[(rl + 8) * XS_STRIDE + col + 1]);
            if (RELU) { o.x = fmaxf(o.x, 0.f); o.y = fmaxf(o.y, 0.f); }
            ((float2*)out)[(size_t)row_hi * 32 + colp] = o;
        }
    }
}

// ---------------- launch ----------------
extern "C" void kernel_launch(void* const* d_in, const int* in_sizes, int n_in,
                              void* d_out, int out_size) {
    const float* x      = (const float*)d_in[0];
    const int*   ei     = (const int*)d_in[1];
    const float* gcn1_w = (const float*)d_in[2];
    const float* gcn1_b = (const float*)d_in[3];
    const float* s1lw   = (const float*)d_in[4];
    const float* s1lb   = (const float*)d_in[5];
    const float* s1rw   = (const float*)d_in[6];
    const float* s2lw   = (const float*)d_in[7];
    const float* s2lb   = (const float*)d_in[8];
    const float* s2rw   = (const float*)d_in[9];
    const float* linw   = (const float*)d_in[10];
    const float* linb   = (const float*)d_in[11];
    const float* gcn2_w = (const float*)d_in[12];
    const float* gcn2_b = (const float*)d_in[13];

    int n = in_sizes[0] / 64;
    int E = in_sizes[1] / 2;
    const int* src = ei;
    const int* dst = ei + E;

    int *degi, *rowptr, *cursor, *csr, *bsums;
    float *dis, *A, *B, *C;
    cudaGetSymbolAddress((void**)&degi, g_degi);
    cudaGetSymbolAddress((void**)&dis, g_dis);
    cudaGetSymbolAddress((void**)&rowptr, g_rowptr);
    cudaGetSymbolAddress((void**)&cursor, g_cursor);
    cudaGetSymbolAddress((void**)&csr, g_csr);
    cudaGetSymbolAddress((void**)&bsums, g_blocksums);
    cudaGetSymbolAddress((void**)&A, g_bufA);
    cudaGetSymbolAddress((void**)&B, g_bufB);
    cudaGetSymbolAddress((void**)&C, g_bufC);

    const int GEMM_SMEM = 64 * WS_STRIDE * 4 + 128 * XS_STRIDE * 4;          // 53248
    const int SAGE_SMEM = 128 * WS_STRIDE * 4 + 2 * 128 * XS_STRIDE * 4;     // 106496
    cudaFuncSetAttribute(gemm_tc_kernel<false, false>, cudaFuncAttributeMaxDynamicSharedMemorySize, GEMM_SMEM);
    cudaFuncSetAttribute(gemm_tc_kernel<true, true>,   cudaFuncAttributeMaxDynamicSharedMemorySize, GEMM_SMEM);
    cudaFuncSetAttribute(sage_tc_kernel<true>,  cudaFuncAttributeMaxDynamicSharedMemorySize, SAGE_SMEM);
    cudaFuncSetAttribute(sage_tc_kernel<false>, cudaFuncAttributeMaxDynamicSharedMemorySize, SAGE_SMEM);

    static cudaStream_t s2 = nullptr;
    static cudaEvent_t evFork = nullptr, evJoin = nullptr;
    if (!s2) {
        cudaStreamCreateWithFlags(&s2, cudaStreamNonBlocking);
        cudaEventCreateWithFlags(&evFork, cudaEventDisableTiming);
        cudaEventCreateWithFlags(&evJoin, cudaEventDisableTiming);
    }

    const int GEMM_GRID = (n + 127) / 128;
    const int GATH_GRID = (n + 31) / 32;
    const int NB = (n + 511) / 512;

    // ---- fork: CSR build on s2, concurrent with gemm1 on main ----
    cudaEventRecord(evFork, 0);
    cudaStreamWaitEvent(s2, evFork, 0);

    cudaMemsetAsync(degi, 0, n * sizeof(int), s2);
    deg_count_kernel<<<(E + 255) / 256, 256, 0, s2>>>(dst, E, degi);
    scan1_kernel<<<NB, 512, 0, s2>>>(degi, rowptr, bsums, dis, n);
    scan2_kernel<<<1, 512, 0, s2>>>(bsums, NB);
    scan3_kernel<<<(n + 512) / 512, 512, 0, s2>>>(rowptr, bsums, cursor, n, E);
    fill_csr_kernel<<<(E + 255) / 256, 256, 0, s2>>>(src, dst, cursor, csr, E);
    cudaEventRecord(evJoin, s2);

    // ---- layer 0 matmul (independent of CSR) ----
    gemm_tc_kernel<false, false><<<GEMM_GRID, 256, GEMM_SMEM>>>(x, gcn1_w, nullptr, A, n);

    cudaStreamWaitEvent(0, evJoin, 0);

    // ---- layer 0: GCN1 + relu ----
    gather_kernel<true, true><<<GATH_GRID, 256>>>(rowptr, csr, A, dis, gcn1_b, C, n);

    // ---- layer 1: SAGE1 + residual + relu ----
    gather_kernel<false, false><<<GATH_GRID, 256>>>(rowptr, csr, C, dis, nullptr, B, n);
    sage_tc_kernel<true><<<GEMM_GRID, 256, SAGE_SMEM>>>(B, C, s1lw, s1lb, s1rw, A, n);

    // ---- layer 2: SAGE2 + residual ----
    gather_kernel<false, false><<<GATH_GRID, 256>>>(rowptr, csr, A, dis, nullptr, B, n);
    sage_tc_kernel<false><<<GEMM_GRID, 256, SAGE_SMEM>>>(B, A, s2lw, s2lb, s2rw, C, n);

    // ---- lin + relu ----
    gemm_tc_kernel<true, true><<<GEMM_GRID, 256, GEMM_SMEM>>>(C, linw, linb, A, n);

    // ---- layer 3: GCN2 ----
    gemm_tc_kernel<false, false><<<GEMM_GRID, 256, GEMM_SMEM>>>(A, gcn2_w, nullptr, C, n);
    gather_kernel<true, false><<<GATH_GRID, 256>>>(rowptr, csr, C, dis, gcn2_b, (float*)d_out, n);
}

// round 8
// speedup vs baseline: 1.0078x; 1.0078x over previous
#include <cuda_runtime.h>
#include <cuda_bf16.h>
#include <cuda_fp16.h>

#define NMAX 100000
#define EMAX 1250000
#define DD 64

// ---------------- scratch ----------------
__device__ int    g_degi[NMAX];
__device__ float  g_dis[NMAX];
__device__ int    g_rowptr[NMAX + 1];
__device__ int    g_cursor[NMAX];
__device__ int    g_csr[EMAX];
__device__ int    g_blocksums[512];
__device__ float  g_bufA[(size_t)NMAX * DD];
__device__ float  g_bufB[(size_t)NMAX * DD];
__device__ float  g_bufC[(size_t)NMAX * DD];
__device__ __half g_h1[(size_t)NMAX * DD];
__device__ __half g_h2[(size_t)NMAX * DD];

// ---------------- tf32 helpers ----------------
__device__ __forceinline__ unsigned f2tf(float f) {
    unsigned u;
    asm("cvt.rna.tf32.f32 %0, %1;" : "=r"(u) : "f"(f));
    return u;
}
__device__ __forceinline__ void mma8(float c[4], unsigned a0, unsigned a1, unsigned a2,
                                     unsigned a3, unsigned b0, unsigned b1) {
    asm("mma.sync.aligned.m16n8k8.row.col.f32.tf32.tf32.f32 "
        "{%0,%1,%2,%3},{%4,%5,%6,%7},{%8,%9},{%0,%1,%2,%3};"
        : "+f"(c[0]), "+f"(c[1]), "+f"(c[2]), "+f"(c[3])
        : "r"(a0), "r"(a1), "r"(a2), "r"(a3), "r"(b0), "r"(b1));
}

// ---------------- fp16 helpers ----------------
__device__ __forceinline__ void acc4h(float4& acc, uint2 u, float w) {
    __half2 h0 = *reinterpret_cast<const __half2*>(&u.x);
    __half2 h1 = *reinterpret_cast<const __half2*>(&u.y);
    float2 f0 = __half22float2(h0), f1 = __half22float2(h1);
    acc.x = fmaf(f0.x, w, acc.x); acc.y = fmaf(f0.y, w, acc.y);
    acc.z = fmaf(f1.x, w, acc.z); acc.w = fmaf(f1.y, w, acc.w);
}
__device__ __forceinline__ void acc4h1(float4& acc, uint2 u) {
    __half2 h0 = *reinterpret_cast<const __half2*>(&u.x);
    __half2 h1 = *reinterpret_cast<const __half2*>(&u.y);
    float2 f0 = __half22float2(h0), f1 = __half22float2(h1);
    acc.x += f0.x; acc.y += f0.y; acc.z += f1.x; acc.w += f1.y;
}
__device__ __forceinline__ uint2 pack_h4(float4 v) {
    __half2 a = __floats2half2_rn(v.x, v.y);
    __half2 b = __floats2half2_rn(v.z, v.w);
    uint2 u;
    u.x = *reinterpret_cast<unsigned*>(&a);
    u.y = *reinterpret_cast<unsigned*>(&b);
    return u;
}

// ---------------- degree ----------------
__global__ void deg_count_kernel(const int* __restrict__ dst, int E, int* __restrict__ degi) {
    int i = blockIdx.x * blockDim.x + threadIdx.x;
    if (i < E) atomicAdd(&degi[dst[i]], 1);
}

// ---------------- exclusive scan (n <= 512*512), fused dis ----------------
__global__ void scan1_kernel(const int* __restrict__ cnt, int* __restrict__ out,
                             int* __restrict__ bsums, float* __restrict__ dis, int n) {
    __shared__ int s[512];
    int i = blockIdx.x * 512 + threadIdx.x;
    int v = (i < n) ? cnt[i] : 0;
    if (i < n) dis[i] = rsqrtf((float)v + 1.0f);
    s[threadIdx.x] = v;
    __syncthreads();
    for (int off = 1; off < 512; off <<= 1) {
        int t = (threadIdx.x >= off) ? s[threadIdx.x - off] : 0;
        __syncthreads();
        s[threadIdx.x] += t;
        __syncthreads();
    }
    if (i < n) out[i] = s[threadIdx.x] - v;
    if (threadIdx.x == 511) bsums[blockIdx.x] = s[511];
}
__global__ void scan2_kernel(int* __restrict__ bsums, int nb) {
    __shared__ int s[512];
    int v = (threadIdx.x < nb) ? bsums[threadIdx.x] : 0;
    s[threadIdx.x] = v;
    __syncthreads();
    for (int off = 1; off < 512; off <<= 1) {
        int t = (threadIdx.x >= off) ? s[threadIdx.x - off] : 0;
        __syncthreads();
        s[threadIdx.x] += t;
        __syncthreads();
    }
    if (threadIdx.x < nb) bsums[threadIdx.x] = s[threadIdx.x] - v;
}
__global__ void scan3_kernel(int* __restrict__ rowptr, const int* __restrict__ bsums,
                             int* __restrict__ cursor, int n, int E) {
    int i = blockIdx.x * 512 + threadIdx.x;
    if (i < n) {
        int v = rowptr[i] + bsums[blockIdx.x];
        rowptr[i] = v;
        cursor[i] = v;
    }
    if (i == n) rowptr[n] = E;
}
__global__ void fill_csr_kernel(const int* __restrict__ src, const int* __restrict__ dst,
                                int* __restrict__ cursor, int* __restrict__ csr, int E) {
    int i = blockIdx.x * blockDim.x + threadIdx.x;
    if (i < E) {
        int pos = atomicAdd(&cursor[dst[i]], 1);
        csr[pos] = src[i];
    }
}

// ---------------- gather (CSR) with fp16 input rows ----------------
// GCN=true : out = relu?(sum_e xw[s]*dis[s]*dis[d] + xw[d]*dis[d]^2 + bias)
// GCN=false: out = (sum_e h[s]) / max(deg,1)
// DUAL: also write fp16 copy of the (post-activation) output.
template <bool GCN, bool RELU, bool DUAL>
__global__ void __launch_bounds__(256) gather_kernel(
    const int* __restrict__ rowptr, const int* __restrict__ csr,
    const __half* __restrict__ xwh, const float* __restrict__ dis,
    const float* __restrict__ bias, float* __restrict__ out,
    __half* __restrict__ outh, int n) {
    int node = blockIdx.x * 16 + (threadIdx.x >> 4);
    int q = threadIdx.x & 15;
    if (node >= n) return;
    int beg = rowptr[node], end = rowptr[node + 1];
    float4 acc = make_float4(0.f, 0.f, 0.f, 0.f);
    const uint2* __restrict__ xv2 = (const uint2*)xwh;   // 4 halfs per uint2, 16 per row
    int e = beg;
    for (; e + 3 < end; e += 4) {
        int s0 = csr[e], s1 = csr[e + 1], s2 = csr[e + 2], s3 = csr[e + 3];
        uint2 u0 = xv2[s0 * 16 + q];
        uint2 u1 = xv2[s1 * 16 + q];
        uint2 u2 = xv2[s2 * 16 + q];
        uint2 u3 = xv2[s3 * 16 + q];
        if (GCN) {
            float w0 = dis[s0], w1 = dis[s1], w2 = dis[s2], w3 = dis[s3];
            acc4h(acc, u0, w0); acc4h(acc, u1, w1);
            acc4h(acc, u2, w2); acc4h(acc, u3, w3);
        } else {
            acc4h1(acc, u0); acc4h1(acc, u1); acc4h1(acc, u2); acc4h1(acc, u3);
        }
    }
    for (; e < end; e++) {
        int s = csr[e];
        uint2 u = xv2[s * 16 + q];
        if (GCN) acc4h(acc, u, dis[s]);
        else     acc4h1(acc, u);
    }
    if (GCN) {
        float dd = dis[node];
        float d2 = dd * dd;
        float4 xv = make_float4(0.f, 0.f, 0.f, 0.f);
        acc4h(xv, xv2[node * 16 + q], 1.0f);
        float4 bb = ((const float4*)bias)[q];
        acc.x = fmaf(acc.x, dd, fmaf(xv.x, d2, bb.x));
        acc.y = fmaf(acc.y, dd, fmaf(xv.y, d2, bb.y));
        acc.z = fmaf(acc.z, dd, fmaf(xv.z, d2, bb.z));
        acc.w = fmaf(acc.w, dd, fmaf(xv.w, d2, bb.w));
        if (RELU) {
            acc.x = fmaxf(acc.x, 0.f); acc.y = fmaxf(acc.y, 0.f);
            acc.z = fmaxf(acc.z, 0.f); acc.w = fmaxf(acc.w, 0.f);
        }
    } else {
        float dinv = 1.0f / fmaxf((float)(end - beg), 1.0f);
        acc.x *= dinv; acc.y *= dinv; acc.z *= dinv; acc.w *= dinv;
    }
    ((float4*)out)[node * 16 + q] = acc;
    if (DUAL) ((uint2*)outh)[node * 16 + q] = pack_h4(acc);
}

// ---------------- tensor-core GEMM: act(X @ W [+ b]) -> fp32 and/or fp16 ----------------
#define XS_STRIDE 68
#define WS_STRIDE 72
template <bool RELU, bool BIAS, bool F32OUT, bool F16OUT>
__global__ void __launch_bounds__(256) gemm_tc_kernel(
    const float* __restrict__ X, const float* __restrict__ W,
    const float* __restrict__ bias, float* __restrict__ out,
    __half* __restrict__ outh, int n) {
    extern __shared__ char smraw[];
    float* Ws = (float*)smraw;
    float* Xs = (float*)(smraw + 64 * WS_STRIDE * 4);
    int tid = threadIdx.x;
    int row0 = blockIdx.x * 128;

    for (int i = tid; i < 4096; i += 256) {
        int k = i >> 6, c = i & 63;
        Ws[k * WS_STRIDE + c] = __uint_as_float(f2tf(W[i]));
    }
    for (int j = tid; j < 2048; j += 256) {
        int r = j >> 4, cg = j & 15;
        float4 v = (row0 + r < n) ? ((const float4*)X)[(size_t)(row0 + r) * 16 + cg]
                                  : make_float4(0.f, 0.f, 0.f, 0.f);
        float* p = &Xs[r * XS_STRIDE + cg * 4];
        p[0] = v.x; p[1] = v.y; p[2] = v.z; p[3] = v.w;
    }
    __syncthreads();

    int warp = tid >> 5;
    int lane = tid & 31;
    int gid = lane >> 2;
    int tig = lane & 3;
    int rlo = warp * 16 + gid;

    float c[8][4];
#pragma unroll
    for (int t = 0; t < 8; t++)
#pragma unroll
        for (int j = 0; j < 4; j++) c[t][j] = 0.f;

#pragma unroll
    for (int ks = 0; ks < 8; ks++) {
        int k0 = ks * 8;
        unsigned a0 = f2tf(Xs[rlo * XS_STRIDE + k0 + tig]);
        unsigned a1 = f2tf(Xs[(rlo + 8) * XS_STRIDE + k0 + tig]);
        unsigned a2 = f2tf(Xs[rlo * XS_STRIDE + k0 + tig + 4]);
        unsigned a3 = f2tf(Xs[(rlo + 8) * XS_STRIDE + k0 + tig + 4]);
#pragma unroll
        for (int t = 0; t < 8; t++) {
            int col = t * 8 + gid;
            unsigned b0 = __float_as_uint(Ws[(k0 + tig) * WS_STRIDE + col]);
            unsigned b1 = __float_as_uint(Ws[(k0 + tig + 4) * WS_STRIDE + col]);
            mma8(c[t], a0, a1, a2, a3, b0, b1);
        }
    }

#pragma unroll
    for (int t = 0; t < 8; t++) {
        int colp = t * 4 + tig;
        float2 bb = BIAS ? ((const float2*)bias)[colp] : make_float2(0.f, 0.f);
        int row_lo = row0 + warp * 16 + gid;
        int row_hi = row_lo + 8;
        if (row_lo < n) {
            float2 o = make_float2(c[t][0] + bb.x, c[t][1] + bb.y);
            if (RELU) { o.x = fmaxf(o.x, 0.f); o.y = fmaxf(o.y, 0.f); }
            if (F32OUT) ((float2*)out)[(size_t)row_lo * 32 + colp] = o;
            if (F16OUT) ((__half2*)outh)[(size_t)row_lo * 32 + colp] = __floats2half2_rn(o.x, o.y);
        }
        if (row_hi < n) {
            float2 o = make_float2(c[t][2] + bb.x, c[t][3] + bb.y);
            if (RELU) { o.x = fmaxf(o.x, 0.f); o.y = fmaxf(o.y, 0.f); }
            if (F32OUT) ((float2*)out)[(size_t)row_hi * 32 + colp] = o;
            if (F16OUT) ((__half2*)outh)[(size_t)row_hi * 32 + colp] = __floats2half2_rn(o.x, o.y);
        }
    }
}

// ---------------- tensor-core SAGE: act(M @ Wl + bl + H @ Wr + H) ----------------
template <bool RELU, bool F16OUT>
__global__ void __launch_bounds__(256) sage_tc_kernel(
    const float* __restrict__ M, const float* __restrict__ H,
    const float* __restrict__ Wl, const float* __restrict__ bl,
    const float* __restrict__ Wr, float* __restrict__ out,
    __half* __restrict__ outh, int n) {
    extern __shared__ char smraw[];
    float* Wc = (float*)smraw;
    float* Ms = (float*)(smraw + 128 * WS_STRIDE * 4);
    float* Hs = (float*)(smraw + 128 * WS_STRIDE * 4 + 128 * XS_STRIDE * 4);
    int tid = threadIdx.x;
    int row0 = blockIdx.x * 128;

    for (int i = tid; i < 4096; i += 256) {
        int k = i >> 6, cc = i & 63;
        Wc[k * WS_STRIDE + cc]        = __uint_as_float(f2tf(Wl[i]));
        Wc[(k + 64) * WS_STRIDE + cc] = __uint_as_float(f2tf(Wr[i]));
    }
    for (int j = tid; j < 2048; j += 256) {
        int r = j >> 4, cg = j & 15;
        float4 m = make_float4(0.f, 0.f, 0.f, 0.f), h = m;
        if (row0 + r < n) {
            m = ((const float4*)M)[(size_t)(row0 + r) * 16 + cg];
            h = ((const float4*)H)[(size_t)(row0 + r) * 16 + cg];
        }
        float* pm = &Ms[r * XS_STRIDE + cg * 4];
        float* ph = &Hs[r * XS_STRIDE + cg * 4];
        pm[0] = m.x; pm[1] = m.y; pm[2] = m.z; pm[3] = m.w;
        ph[0] = h.x; ph[1] = h.y; ph[2] = h.z; ph[3] = h.w;
    }
    __syncthreads();

    int warp = tid >> 5;
    int lane = tid & 31;
    int gid = lane >> 2;
    int tig = lane & 3;
    int rlo = warp * 16 + gid;

    float c[8][4];
#pragma unroll
    for (int t = 0; t < 8; t++)
#pragma unroll
        for (int j = 0; j < 4; j++) c[t][j] = 0.f;

#pragma unroll
    for (int ks = 0; ks < 16; ks++) {
        const float* A = (ks < 8) ? Ms : Hs;
        int k0 = (ks & 7) * 8;
        int kw = ks * 8;
        unsigned a0 = f2tf(A[rlo * XS_STRIDE + k0 + tig]);
        unsigned a1 = f2tf(A[(rlo + 8) * XS_STRIDE + k0 + tig]);
        unsigned a2 = f2tf(A[rlo * XS_STRIDE + k0 + tig + 4]);
        unsigned a3 = f2tf(A[(rlo + 8) * XS_STRIDE + k0 + tig + 4]);
#pragma unroll
        for (int t = 0; t < 8; t++) {
            int col = t * 8 + gid;
            unsigned b0 = __float_as_uint(Wc[(kw + tig) * WS_STRIDE + col]);
            unsigned b1 = __float_as_uint(Wc[(kw + tig + 4) * WS_STRIDE + col]);
            mma8(c[t], a0, a1, a2, a3, b0, b1);
        }
    }

#pragma unroll
    for (int t = 0; t < 8; t++) {
        int colp = t * 4 + tig;
        int col = colp * 2;
        float2 bb = ((const float2*)bl)[colp];
        int rl = warp * 16 + gid;
        int row_lo = row0 + rl;
        int row_hi = row_lo + 8;
        if (row_lo < n) {
            float2 o = make_float2(c[t][0] + bb.x + Hs[rl * XS_STRIDE + col],
                                   c[t][1] + bb.y + Hs[rl * XS_STRIDE + col + 1]);
            if (RELU) { o.x = fmaxf(o.x, 0.f); o.y = fmaxf(o.y, 0.f); }
            ((float2*)out)[(size_t)row_lo * 32 + colp] = o;
            if (F16OUT) ((__half2*)outh)[(size_t)row_lo * 32 + colp] = __floats2half2_rn(o.x, o.y);
        }
        if (row_hi < n) {
            float2 o = make_float2(c[t][2] + bb.x + Hs[(rl + 8) * XS_STRIDE + col],
                                   c[t][3] + bb.y + Hs[(rl + 8) * XS_STRIDE + col + 1]);
            if (RELU) { o.x = fmaxf(o.x, 0.f); o.y = fmaxf(o.y, 0.f); }
            ((float2*)out)[(size_t)row_hi * 32 + colp] = o;
            if (F16OUT) ((__half2*)outh)[(size_t)row_hi * 32 + colp] = __floats2half2_rn(o.x, o.y);
        }
    }
}

// ---------------- launch ----------------
extern "C" void kernel_launch(void* const* d_in, const int* in_sizes, int n_in,
                              void* d_out, int out_size) {
    const float* x      = (const float*)d_in[0];
    const int*   ei     = (const int*)d_in[1];
    const float* gcn1_w = (const float*)d_in[2];
    const float* gcn1_b = (const float*)d_in[3];
    const float* s1lw   = (const float*)d_in[4];
    const float* s1lb   = (const float*)d_in[5];
    const float* s1rw   = (const float*)d_in[6];
    const float* s2lw   = (const float*)d_in[7];
    const float* s2lb   = (const float*)d_in[8];
    const float* s2rw   = (const float*)d_in[9];
    const float* linw   = (const float*)d_in[10];
    const float* linb   = (const float*)d_in[11];
    const float* gcn2_w = (const float*)d_in[12];
    const float* gcn2_b = (const float*)d_in[13];

    int n = in_sizes[0] / 64;
    int E = in_sizes[1] / 2;
    const int* src = ei;
    const int* dst = ei + E;

    int *degi, *rowptr, *cursor, *csr, *bsums;
    float *dis, *A, *B, *C;
    __half *H1, *H2;
    cudaGetSymbolAddress((void**)&degi, g_degi);
    cudaGetSymbolAddress((void**)&dis, g_dis);
    cudaGetSymbolAddress((void**)&rowptr, g_rowptr);
    cudaGetSymbolAddress((void**)&cursor, g_cursor);
    cudaGetSymbolAddress((void**)&csr, g_csr);
    cudaGetSymbolAddress((void**)&bsums, g_blocksums);
    cudaGetSymbolAddress((void**)&A, g_bufA);
    cudaGetSymbolAddress((void**)&B, g_bufB);
    cudaGetSymbolAddress((void**)&C, g_bufC);
    cudaGetSymbolAddress((void**)&H1, g_h1);
    cudaGetSymbolAddress((void**)&H2, g_h2);

    const int GEMM_SMEM = 64 * WS_STRIDE * 4 + 128 * XS_STRIDE * 4;          // 53248
    const int SAGE_SMEM = 128 * WS_STRIDE * 4 + 2 * 128 * XS_STRIDE * 4;     // 106496
    cudaFuncSetAttribute(gemm_tc_kernel<false, false, false, true>, cudaFuncAttributeMaxDynamicSharedMemorySize, GEMM_SMEM);
    cudaFuncSetAttribute(gemm_tc_kernel<true, true, true, false>,   cudaFuncAttributeMaxDynamicSharedMemorySize, GEMM_SMEM);
    cudaFuncSetAttribute(sage_tc_kernel<true, true>,   cudaFuncAttributeMaxDynamicSharedMemorySize, SAGE_SMEM);
    cudaFuncSetAttribute(sage_tc_kernel<false, false>, cudaFuncAttributeMaxDynamicSharedMemorySize, SAGE_SMEM);

    static cudaStream_t s2 = nullptr;
    static cudaEvent_t evFork = nullptr, evJoin = nullptr;
    if (!s2) {
        cudaStreamCreateWithFlags(&s2, cudaStreamNonBlocking);
        cudaEventCreateWithFlags(&evFork, cudaEventDisableTiming);
        cudaEventCreateWithFlags(&evJoin, cudaEventDisableTiming);
    }

    const int GEMM_GRID = (n + 127) / 128;
    const int GATH_GRID = (n + 15) / 16;
    const int NB = (n + 511) / 512;

    // ---- fork: CSR build on s2, concurrent with gemm1 on main ----
    cudaEventRecord(evFork, 0);
    cudaStreamWaitEvent(s2, evFork, 0);

    cudaMemsetAsync(degi, 0, n * sizeof(int), s2);
    deg_count_kernel<<<(E + 255) / 256, 256, 0, s2>>>(dst, E, degi);
    scan1_kernel<<<NB, 512, 0, s2>>>(degi, rowptr, bsums, dis, n);
    scan2_kernel<<<1, 512, 0, s2>>>(bsums, NB);
    scan3_kernel<<<(n + 512) / 512, 512, 0, s2>>>(rowptr, bsums, cursor, n, E);
    fill_csr_kernel<<<(E + 255) / 256, 256, 0, s2>>>(src, dst, cursor, csr, E);
    cudaEventRecord(evJoin, s2);

    // ---- layer 0 matmul: xw -> fp16 only (only gather1 consumes it) ----
    gemm_tc_kernel<false, false, false, true><<<GEMM_GRID, 256, GEMM_SMEM>>>(
        x, gcn1_w, nullptr, nullptr, H1, n);

    cudaStreamWaitEvent(0, evJoin, 0);

    // ---- layer 0: GCN1 + relu -> C (fp32) + H2 (fp16) ----
    gather_kernel<true, true, true><<<GATH_GRID, 256>>>(rowptr, csr, H1, dis, gcn1_b, C, H2, n);

    // ---- layer 1: SAGE1 + residual + relu ----
    gather_kernel<false, false, false><<<GATH_GRID, 256>>>(rowptr, csr, H2, dis, nullptr, B, nullptr, n);
    sage_tc_kernel<true, true><<<GEMM_GRID, 256, SAGE_SMEM>>>(B, C, s1lw, s1lb, s1rw, A, H1, n);

    // ---- layer 2: SAGE2 + residual ----
    gather_kernel<false, false, false><<<GATH_GRID, 256>>>(rowptr, csr, H1, dis, nullptr, B, nullptr, n);
    sage_tc_kernel<false, false><<<GEMM_GRID, 256, SAGE_SMEM>>>(B, A, s2lw, s2lb, s2rw, C, nullptr, n);

    // ---- lin + relu (fp32 only) ----
    gemm_tc_kernel<true, true, true, false><<<GEMM_GRID, 256, GEMM_SMEM>>>(
        C, linw, linb, A, nullptr, n);

    // ---- layer 3: GCN2: xw -> fp16 only; gather -> d_out fp32 ----
    gemm_tc_kernel<false, false, false, true><<<GEMM_GRID, 256, GEMM_SMEM>>>(
        A, gcn2_w, nullptr, nullptr, H2, n);
    gather_kernel<true, false, false><<<GATH_GRID, 256>>>(rowptr, csr, H2, dis, gcn2_b, (float*)d_out, nullptr, n);
}

// round 9
// speedup vs baseline: 1.2290x; 1.2195x over previous
#include <cuda_runtime.h>
#include <cuda_bf16.h>
#include <cuda_fp16.h>

#define NMAX 100000
#define EMAX 1250000
#define DD 64

// ---------------- scratch ----------------
__device__ int    g_degi[NMAX];
__device__ float  g_dis[NMAX];
__device__ int    g_rowptr[NMAX + 1];
__device__ int    g_cursor[NMAX];
__device__ int    g_csr[EMAX];
__device__ int    g_blocksums[512];
__device__ __half g_hA[(size_t)NMAX * DD];
__device__ __half g_hB[(size_t)NMAX * DD];
__device__ __half g_hC[(size_t)NMAX * DD];
__device__ __half g_hM[(size_t)NMAX * DD];

// ---------------- fp16 mma helper ----------------
__device__ __forceinline__ void mma16(float c[4], unsigned a0, unsigned a1, unsigned a2,
                                      unsigned a3, unsigned b0, unsigned b1) {
    asm("mma.sync.aligned.m16n8k16.row.col.f32.f16.f16.f32 "
        "{%0,%1,%2,%3},{%4,%5,%6,%7},{%8,%9},{%0,%1,%2,%3};"
        : "+f"(c[0]), "+f"(c[1]), "+f"(c[2]), "+f"(c[3])
        : "r"(a0), "r"(a1), "r"(a2), "r"(a3), "r"(b0), "r"(b1));
}

__device__ __forceinline__ void acc4h(float4& acc, uint2 u, float w) {
    __half2 h0 = *reinterpret_cast<const __half2*>(&u.x);
    __half2 h1 = *reinterpret_cast<const __half2*>(&u.y);
    float2 f0 = __half22float2(h0), f1 = __half22float2(h1);
    acc.x = fmaf(f0.x, w, acc.x); acc.y = fmaf(f0.y, w, acc.y);
    acc.z = fmaf(f1.x, w, acc.z); acc.w = fmaf(f1.y, w, acc.w);
}
__device__ __forceinline__ void acc4h1(float4& acc, uint2 u) {
    __half2 h0 = *reinterpret_cast<const __half2*>(&u.x);
    __half2 h1 = *reinterpret_cast<const __half2*>(&u.y);
    float2 f0 = __half22float2(h0), f1 = __half22float2(h1);
    acc.x += f0.x; acc.y += f0.y; acc.z += f1.x; acc.w += f1.y;
}
__device__ __forceinline__ uint2 pack_h4(float4 v) {
    __half2 a = __floats2half2_rn(v.x, v.y);
    __half2 b = __floats2half2_rn(v.z, v.w);
    uint2 u;
    u.x = *reinterpret_cast<unsigned*>(&a);
    u.y = *reinterpret_cast<unsigned*>(&b);
    return u;
}

// ---------------- degree ----------------
__global__ void deg_count_kernel(const int* __restrict__ dst, int E, int* __restrict__ degi) {
    int i = blockIdx.x * blockDim.x + threadIdx.x;
    if (i < E) atomicAdd(&degi[dst[i]], 1);
}

// ---------------- exclusive scan, fused dis ----------------
__global__ void scan1_kernel(const int* __restrict__ cnt, int* __restrict__ out,
                             int* __restrict__ bsums, float* __restrict__ dis, int n) {
    __shared__ int s[512];
    int i = blockIdx.x * 512 + threadIdx.x;
    int v = (i < n) ? cnt[i] : 0;
    if (i < n) dis[i] = rsqrtf((float)v + 1.0f);
    s[threadIdx.x] = v;
    __syncthreads();
    for (int off = 1; off < 512; off <<= 1) {
        int t = (threadIdx.x >= off) ? s[threadIdx.x - off] : 0;
        __syncthreads();
        s[threadIdx.x] += t;
        __syncthreads();
    }
    if (i < n) out[i] = s[threadIdx.x] - v;
    if (threadIdx.x == 511) bsums[blockIdx.x] = s[511];
}
__global__ void scan2_kernel(int* __restrict__ bsums, int nb) {
    __shared__ int s[512];
    int v = (threadIdx.x < nb) ? bsums[threadIdx.x] : 0;
    s[threadIdx.x] = v;
    __syncthreads();
    for (int off = 1; off < 512; off <<= 1) {
        int t = (threadIdx.x >= off) ? s[threadIdx.x - off] : 0;
        __syncthreads();
        s[threadIdx.x] += t;
        __syncthreads();
    }
    if (threadIdx.x < nb) bsums[threadIdx.x] = s[threadIdx.x] - v;
}
__global__ void scan3_kernel(int* __restrict__ rowptr, const int* __restrict__ bsums,
                             int* __restrict__ cursor, int n, int E) {
    int i = blockIdx.x * 512 + threadIdx.x;
    if (i < n) {
        int v = rowptr[i] + bsums[blockIdx.x];
        rowptr[i] = v;
        cursor[i] = v;
    }
    if (i == n) rowptr[n] = E;
}
__global__ void fill_csr_kernel(const int* __restrict__ src, const int* __restrict__ dst,
                                int* __restrict__ cursor, int* __restrict__ csr, int E) {
    int i = blockIdx.x * blockDim.x + threadIdx.x;
    if (i < E) {
        int pos = atomicAdd(&cursor[dst[i]], 1);
        csr[pos] = src[i];
    }
}

// ---------------- gather (CSR), fp16 rows in; fp16 or fp32 out ----------------
template <bool GCN, bool RELU, bool OUTF32>
__global__ void __launch_bounds__(256) gather_kernel(
    const int* __restrict__ rowptr, const int* __restrict__ csr,
    const __half* __restrict__ xwh, const float* __restrict__ dis,
    const float* __restrict__ bias, float* __restrict__ outf,
    __half* __restrict__ outh, int n) {
    int node = blockIdx.x * 16 + (threadIdx.x >> 4);
    int q = threadIdx.x & 15;
    if (node >= n) return;
    int beg = rowptr[node], end = rowptr[node + 1];
    float4 acc = make_float4(0.f, 0.f, 0.f, 0.f);
    const uint2* __restrict__ xv2 = (const uint2*)xwh;
    int e = beg;
    for (; e + 3 < end; e += 4) {
        int s0 = csr[e], s1 = csr[e + 1], s2 = csr[e + 2], s3 = csr[e + 3];
        uint2 u0 = xv2[s0 * 16 + q];
        uint2 u1 = xv2[s1 * 16 + q];
        uint2 u2 = xv2[s2 * 16 + q];
        uint2 u3 = xv2[s3 * 16 + q];
        if (GCN) {
            float w0 = dis[s0], w1 = dis[s1], w2 = dis[s2], w3 = dis[s3];
            acc4h(acc, u0, w0); acc4h(acc, u1, w1);
            acc4h(acc, u2, w2); acc4h(acc, u3, w3);
        } else {
            acc4h1(acc, u0); acc4h1(acc, u1); acc4h1(acc, u2); acc4h1(acc, u3);
        }
    }
    for (; e < end; e++) {
        int s = csr[e];
        uint2 u = xv2[s * 16 + q];
        if (GCN) acc4h(acc, u, dis[s]);
        else     acc4h1(acc, u);
    }
    if (GCN) {
        float dd = dis[node];
        float d2 = dd * dd;
        float4 xv = make_float4(0.f, 0.f, 0.f, 0.f);
        acc4h(xv, xv2[node * 16 + q], 1.0f);
        float4 bb = ((const float4*)bias)[q];
        acc.x = fmaf(acc.x, dd, fmaf(xv.x, d2, bb.x));
        acc.y = fmaf(acc.y, dd, fmaf(xv.y, d2, bb.y));
        acc.z = fmaf(acc.z, dd, fmaf(xv.z, d2, bb.z));
        acc.w = fmaf(acc.w, dd, fmaf(xv.w, d2, bb.w));
        if (RELU) {
            acc.x = fmaxf(acc.x, 0.f); acc.y = fmaxf(acc.y, 0.f);
            acc.z = fmaxf(acc.z, 0.f); acc.w = fmaxf(acc.w, 0.f);
        }
    } else {
        float dinv = 1.0f / fmaxf((float)(end - beg), 1.0f);
        acc.x *= dinv; acc.y *= dinv; acc.z *= dinv; acc.w *= dinv;
    }
    if (OUTF32) ((float4*)outf)[node * 16 + q] = acc;
    else        ((uint2*)outh)[node * 16 + q] = pack_h4(acc);
}

// ---------------- fp16 tensor-core GEMM: out = act(X @ W [+ b]) -> fp16 ----------------
// smem: Wt[64 cols][72 k] fp16 (col-major for B frags), Xh[128][72] fp16.
template <bool RELU, bool BIAS, bool INHALF>
__global__ void __launch_bounds__(256) gemm_h_kernel(
    const float* __restrict__ Xf, const __half* __restrict__ Xh_in,
    const float* __restrict__ W, const float* __restrict__ bias,
    __half* __restrict__ outh, int n) {
    __shared__ __half Wt[64 * 72];
    __shared__ __half Xh[128 * 72];
    int tid = threadIdx.x;
    int row0 = blockIdx.x * 128;

    for (int i = tid; i < 4096; i += 256) {
        int k = i >> 6, c = i & 63;
        Wt[c * 72 + k] = __float2half(W[i]);       // transpose: Wt[col][k]
    }
    for (int j = tid; j < 2048; j += 256) {
        int r = j >> 4, cg = j & 15;
        uint2 u = make_uint2(0u, 0u);
        if (row0 + r < n) {
            if (INHALF) {
                u = ((const uint2*)Xh_in)[(size_t)(row0 + r) * 16 + cg];
            } else {
                float4 v = ((const float4*)Xf)[(size_t)(row0 + r) * 16 + cg];
                u = pack_h4(v);
            }
        }
        *reinterpret_cast<uint2*>(&Xh[r * 72 + cg * 4]) = u;
    }
    __syncthreads();

    int warp = tid >> 5;
    int lane = tid & 31;
    int gid = lane >> 2;       // 0..7
    int tig = lane & 3;        // 0..3
    int rlo = warp * 16 + gid;

    float c[8][4];
#pragma unroll
    for (int t = 0; t < 8; t++)
#pragma unroll
        for (int j = 0; j < 4; j++) c[t][j] = 0.f;

#pragma unroll
    for (int ks = 0; ks < 4; ks++) {
        int k0 = ks * 16;
        unsigned a0 = *reinterpret_cast<const unsigned*>(&Xh[rlo * 72 + k0 + tig * 2]);
        unsigned a1 = *reinterpret_cast<const unsigned*>(&Xh[(rlo + 8) * 72 + k0 + tig * 2]);
        unsigned a2 = *reinterpret_cast<const unsigned*>(&Xh[rlo * 72 + k0 + 8 + tig * 2]);
        unsigned a3 = *reinterpret_cast<const unsigned*>(&Xh[(rlo + 8) * 72 + k0 + 8 + tig * 2]);
#pragma unroll
        for (int t = 0; t < 8; t++) {
            int col = t * 8 + gid;
            unsigned b0 = *reinterpret_cast<const unsigned*>(&Wt[col * 72 + k0 + tig * 2]);
            unsigned b1 = *reinterpret_cast<const unsigned*>(&Wt[col * 72 + k0 + 8 + tig * 2]);
            mma16(c[t], a0, a1, a2, a3, b0, b1);
        }
    }

#pragma unroll
    for (int t = 0; t < 8; t++) {
        int colp = t * 4 + tig;   // half2 index; global cols t*8+tig*2,+1
        float2 bb = BIAS ? ((const float2*)bias)[colp] : make_float2(0.f, 0.f);
        int row_lo = row0 + warp * 16 + gid;
        int row_hi = row_lo + 8;
        if (row_lo < n) {
            float ox = c[t][0] + bb.x, oy = c[t][1] + bb.y;
            if (RELU) { ox = fmaxf(ox, 0.f); oy = fmaxf(oy, 0.f); }
            ((__half2*)outh)[(size_t)row_lo * 32 + colp] = __floats2half2_rn(ox, oy);
        }
        if (row_hi < n) {
            float ox = c[t][2] + bb.x, oy = c[t][3] + bb.y;
            if (RELU) { ox = fmaxf(ox, 0.f); oy = fmaxf(oy, 0.f); }
            ((__half2*)outh)[(size_t)row_hi * 32 + colp] = __floats2half2_rn(ox, oy);
        }
    }
}

// ---------------- fp16 SAGE: out = act(M @ Wl + bl + H @ Wr + H) -> fp16 ----------------
// dyn smem: Wc[64 cols][136 k] fp16 (k<64: Wl, k>=64: Wr) 17408B + Mh[128][72] 18432 + Hh[128][72] 18432
template <bool RELU>
__global__ void __launch_bounds__(256) sage_h_kernel(
    const __half* __restrict__ M, const __half* __restrict__ H,
    const float* __restrict__ Wl, const float* __restrict__ bl,
    const float* __restrict__ Wr, __half* __restrict__ outh, int n) {
    extern __shared__ char smraw[];
    __half* Wc = (__half*)smraw;                    // [64 cols][136 k]
    __half* Mh = (__half*)(smraw + 17408);          // [128][72]
    __half* Hh = (__half*)(smraw + 17408 + 18432);  // [128][72]
    int tid = threadIdx.x;
    int row0 = blockIdx.x * 128;

    for (int i = tid; i < 4096; i += 256) {
        int k = i >> 6, cc = i & 63;
        Wc[cc * 136 + k]      = __float2half(Wl[i]);
        Wc[cc * 136 + 64 + k] = __float2half(Wr[i]);
    }
    for (int j = tid; j < 2048; j += 256) {
        int r = j >> 4, cg = j & 15;
        uint2 um = make_uint2(0u, 0u), uh = um;
        if (row0 + r < n) {
            um = ((const uint2*)M)[(size_t)(row0 + r) * 16 + cg];
            uh = ((const uint2*)H)[(size_t)(row0 + r) * 16 + cg];
        }
        *reinterpret_cast<uint2*>(&Mh[r * 72 + cg * 4]) = um;
        *reinterpret_cast<uint2*>(&Hh[r * 72 + cg * 4]) = uh;
    }
    __syncthreads();

    int warp = tid >> 5;
    int lane = tid & 31;
    int gid = lane >> 2;
    int tig = lane & 3;
    int rlo = warp * 16 + gid;

    float c[8][4];
#pragma unroll
    for (int t = 0; t < 8; t++)
#pragma unroll
        for (int j = 0; j < 4; j++) c[t][j] = 0.f;

#pragma unroll
    for (int ks = 0; ks < 8; ks++) {
        const __half* A = (ks < 4) ? Mh : Hh;
        int k0 = (ks & 3) * 16;      // within A tile
        int kw = ks * 16;            // within Wc (global K=128)
        unsigned a0 = *reinterpret_cast<const unsigned*>(&A[rlo * 72 + k0 + tig * 2]);
        unsigned a1 = *reinterpret_cast<const unsigned*>(&A[(rlo + 8) * 72 + k0 + tig * 2]);
        unsigned a2 = *reinterpret_cast<const unsigned*>(&A[rlo * 72 + k0 + 8 + tig * 2]);
        unsigned a3 = *reinterpret_cast<const unsigned*>(&A[(rlo + 8) * 72 + k0 + 8 + tig * 2]);
#pragma unroll
        for (int t = 0; t < 8; t++) {
            int col = t * 8 + gid;
            unsigned b0 = *reinterpret_cast<const unsigned*>(&Wc[col * 136 + kw + tig * 2]);
            unsigned b1 = *reinterpret_cast<const unsigned*>(&Wc[col * 136 + kw + 8 + tig * 2]);
            mma16(c[t], a0, a1, a2, a3, b0, b1);
        }
    }

#pragma unroll
    for (int t = 0; t < 8; t++) {
        int colp = t * 4 + tig;
        int col = t * 8 + tig * 2;
        float2 bb = ((const float2*)bl)[colp];
        int rl = warp * 16 + gid;
        int row_lo = row0 + rl;
        int row_hi = row_lo + 8;
        if (row_lo < n) {
            float2 hres = __half22float2(*reinterpret_cast<const __half2*>(&Hh[rl * 72 + col]));
            float ox = c[t][0] + bb.x + hres.x, oy = c[t][1] + bb.y + hres.y;
            if (RELU) { ox = fmaxf(ox, 0.f); oy = fmaxf(oy, 0.f); }
            ((__half2*)outh)[(size_t)row_lo * 32 + colp] = __floats2half2_rn(ox, oy);
        }
        if (row_hi < n) {
            float2 hres = __half22float2(*reinterpret_cast<const __half2*>(&Hh[(rl + 8) * 72 + col]));
            float ox = c[t][2] + bb.x + hres.x, oy = c[t][3] + bb.y + hres.y;
            if (RELU) { ox = fmaxf(ox, 0.f); oy = fmaxf(oy, 0.f); }
            ((__half2*)outh)[(size_t)row_hi * 32 + colp] = __floats2half2_rn(ox, oy);
        }
    }
}

// ---------------- launch ----------------
extern "C" void kernel_launch(void* const* d_in, const int* in_sizes, int n_in,
                              void* d_out, int out_size) {
    const float* x      = (const float*)d_in[0];
    const int*   ei     = (const int*)d_in[1];
    const float* gcn1_w = (const float*)d_in[2];
    const float* gcn1_b = (const float*)d_in[3];
    const float* s1lw   = (const float*)d_in[4];
    const float* s1lb   = (const float*)d_in[5];
    const float* s1rw   = (const float*)d_in[6];
    const float* s2lw   = (const float*)d_in[7];
    const float* s2lb   = (const float*)d_in[8];
    const float* s2rw   = (const float*)d_in[9];
    const float* linw   = (const float*)d_in[10];
    const float* linb   = (const float*)d_in[11];
    const float* gcn2_w = (const float*)d_in[12];
    const float* gcn2_b = (const float*)d_in[13];

    int n = in_sizes[0] / 64;
    int E = in_sizes[1] / 2;
    const int* src = ei;
    const int* dst = ei + E;

    int *degi, *rowptr, *cursor, *csr, *bsums;
    float *dis;
    __half *hA, *hB, *hC, *hM;
    cudaGetSymbolAddress((void**)&degi, g_degi);
    cudaGetSymbolAddress((void**)&dis, g_dis);
    cudaGetSymbolAddress((void**)&rowptr, g_rowptr);
    cudaGetSymbolAddress((void**)&cursor, g_cursor);
    cudaGetSymbolAddress((void**)&csr, g_csr);
    cudaGetSymbolAddress((void**)&bsums, g_blocksums);
    cudaGetSymbolAddress((void**)&hA, g_hA);
    cudaGetSymbolAddress((void**)&hB, g_hB);
    cudaGetSymbolAddress((void**)&hC, g_hC);
    cudaGetSymbolAddress((void**)&hM, g_hM);

    const int SAGE_SMEM = 17408 + 2 * 18432;   // 54272
    cudaFuncSetAttribute(sage_h_kernel<true>,  cudaFuncAttributeMaxDynamicSharedMemorySize, SAGE_SMEM);
    cudaFuncSetAttribute(sage_h_kernel<false>, cudaFuncAttributeMaxDynamicSharedMemorySize, SAGE_SMEM);

    static cudaStream_t s2 = nullptr;
    static cudaEvent_t evFork = nullptr, evJoin = nullptr;
    if (!s2) {
        cudaStreamCreateWithFlags(&s2, cudaStreamNonBlocking);
        cudaEventCreateWithFlags(&evFork, cudaEventDisableTiming);
        cudaEventCreateWithFlags(&evJoin, cudaEventDisableTiming);
    }

    const int GEMM_GRID = (n + 127) / 128;
    const int GATH_GRID = (n + 15) / 16;
    const int NB = (n + 511) / 512;

    // ---- fork: CSR build on s2, concurrent with gemm1 on main ----
    cudaEventRecord(evFork, 0);
    cudaStreamWaitEvent(s2, evFork, 0);

    cudaMemsetAsync(degi, 0, n * sizeof(int), s2);
    deg_count_kernel<<<(E + 255) / 256, 256, 0, s2>>>(dst, E, degi);
    scan1_kernel<<<NB, 512, 0, s2>>>(degi, rowptr, bsums, dis, n);
    scan2_kernel<<<1, 512, 0, s2>>>(bsums, NB);
    scan3_kernel<<<(n + 512) / 512, 512, 0, s2>>>(rowptr, bsums, cursor, n, E);
    fill_csr_kernel<<<(E + 255) / 256, 256, 0, s2>>>(src, dst, cursor, csr, E);
    cudaEventRecord(evJoin, s2);

    // ---- layer 0 matmul: xw = x @ gcn1_w -> hA (fp16) ----
    gemm_h_kernel<false, false, false><<<GEMM_GRID, 256>>>(x, nullptr, gcn1_w, nullptr, hA, n);

    cudaStreamWaitEvent(0, evJoin, 0);

    // ---- layer 0: GCN1 + relu -> hB ----
    gather_kernel<true, true, false><<<GATH_GRID, 256>>>(rowptr, csr, hA, dis, gcn1_b, nullptr, hB, n);

    // ---- layer 1: SAGE1 + residual + relu -> hA ----
    gather_kernel<false, false, false><<<GATH_GRID, 256>>>(rowptr, csr, hB, dis, nullptr, nullptr, hM, n);
    sage_h_kernel<true><<<GEMM_GRID, 256, SAGE_SMEM>>>(hM, hB, s1lw, s1lb, s1rw, hA, n);

    // ---- layer 2: SAGE2 + residual -> hC ----
    gather_kernel<false, false, false><<<GATH_GRID, 256>>>(rowptr, csr, hA, dis, nullptr, nullptr, hM, n);
    sage_h_kernel<false><<<GEMM_GRID, 256, SAGE_SMEM>>>(hM, hA, s2lw, s2lb, s2rw, hC, n);

    // ---- lin + relu -> hA ----
    gemm_h_kernel<true, true, true><<<GEMM_GRID, 256>>>(nullptr, hC, linw, linb, hA, n);

    // ---- layer 3: GCN2: xw -> hB; gather -> d_out (fp32) ----
    gemm_h_kernel<false, false, true><<<GEMM_GRID, 256>>>(nullptr, hA, gcn2_w, nullptr, hB, n);
    gather_kernel<true, false, true><<<GATH_GRID, 256>>>(rowptr, csr, hB, dis, gcn2_b, (float*)d_out, nullptr, n);
}